// round 3
// baseline (speedup 1.0000x reference)
#include <cuda_runtime.h>
#include <math_constants.h>

#define K_LEN 1024
#define I_LEN 8192
#define DIM   128

#define CPT   8                 // columns per thread in the systolic chain
#define NW    32                // single-warp CTAs; 32*32*8 = 8192 columns
#define STEPS_PAD 1056          // K_LEN + 31 padded to multiple of 3
#define SROWS 2048              // skewed-matrix rows: m + n/8 in [0, 2046]

// Scratch (alloc-free rule: __device__ globals)
__device__ float g_S[SROWS * I_LEN];          // 64 MB skewed cost: S[m+n/8][n]=C[m][n]
__device__ float g_k2[K_LEN];
__device__ float g_x2[I_LEN];
// cross-CTA boundary slots, one per (cta, global step): (valbits<<32)|(s+1)
__device__ unsigned long long g_bnd[NW][2048];

__device__ __forceinline__ unsigned long long ld_acq(const unsigned long long* p) {
    unsigned long long v;
    asm volatile("ld.global.acquire.gpu.b64 %0, [%1];" : "=l"(v) : "l"(p));
    return v;
}
__device__ __forceinline__ void st_rel(unsigned long long* p, unsigned long long v) {
    asm volatile("st.global.release.gpu.b64 [%0], %1;" :: "l"(p), "l"(v));
}

// ---------------------------------------------------------------------------
// Kernel 1: row norms + zero boundary slots + zero extra out elements.
// ---------------------------------------------------------------------------
__global__ void norms_kernel(const float* __restrict__ kern,
                             const float* __restrict__ x,
                             float* __restrict__ out, int out_size) {
    int gtid = blockIdx.x * blockDim.x + threadIdx.x;
    if (gtid < NW * 2048) ((unsigned long long*)g_bnd)[gtid] = 0ull;
    if (gtid < out_size) out[gtid] = 0.0f;    // out[0] overwritten by DP

    int warp = gtid >> 5;
    int lane = threadIdx.x & 31;
    if (warp >= K_LEN + I_LEN) return;
    const float* row = (warp < K_LEN) ? (kern + warp * DIM)
                                      : (x + (warp - K_LEN) * DIM);
    float4 v = ((const float4*)row)[lane];
    float s = v.x * v.x + v.y * v.y + v.z * v.z + v.w * v.w;
#pragma unroll
    for (int off = 16; off; off >>= 1) s += __shfl_xor_sync(0xffffffffu, s, off);
    if (lane == 0) {
        if (warp < K_LEN) g_k2[warp] = s;
        else              g_x2[warp - K_LEN] = s;
    }
}

// ---------------------------------------------------------------------------
// Kernel 2: skewed cost matrix S[m + n/8][n] = max(k2[m]+x2[n]-2<a_m,b_n>, 0)
// Plain scalar-FFMA tiled SGEMM (R1 version), only the epilogue is skewed.
// ---------------------------------------------------------------------------
#define BM 64
#define BN 64
#define BK 64

__global__ __launch_bounds__(256) void cost_gemm(const float* __restrict__ A,
                                                 const float* __restrict__ B) {
    __shared__ float As[BK][BM + 4];
    __shared__ float Bs[BK][BN + 4];
    const int tx = threadIdx.x & 15;
    const int ty = threadIdx.x >> 4;
    const int m0 = blockIdx.y * BM;
    const int n0 = blockIdx.x * BN;
    const int t  = threadIdx.x;

    float acc[4][4] = {};

    for (int k0 = 0; k0 < DIM; k0 += BK) {
#pragma unroll
        for (int i = 0; i < 4; i++) {
            int idx = t + i * 256;
            int row = idx >> 4;
            int c4  = idx & 15;
            float4 va = *(const float4*)(A + (size_t)(m0 + row) * DIM + k0 + c4 * 4);
            As[c4 * 4 + 0][row] = va.x;
            As[c4 * 4 + 1][row] = va.y;
            As[c4 * 4 + 2][row] = va.z;
            As[c4 * 4 + 3][row] = va.w;
            float4 vb = *(const float4*)(B + (size_t)(n0 + row) * DIM + k0 + c4 * 4);
            Bs[c4 * 4 + 0][row] = vb.x;
            Bs[c4 * 4 + 1][row] = vb.y;
            Bs[c4 * 4 + 2][row] = vb.z;
            Bs[c4 * 4 + 3][row] = vb.w;
        }
        __syncthreads();
#pragma unroll 16
        for (int kk = 0; kk < BK; kk++) {
            float a[4], b[4];
            *(float4*)a = *(const float4*)&As[kk][ty * 4];
            *(float4*)b = *(const float4*)&Bs[kk][tx * 4];
#pragma unroll
            for (int i = 0; i < 4; i++)
#pragma unroll
                for (int j = 0; j < 4; j++)
                    acc[i][j] += a[i] * b[j];
        }
        __syncthreads();
    }

    const int n = n0 + tx * 4;                 // 4 cols, never cross an 8-boundary
#pragma unroll
    for (int i = 0; i < 4; i++) {
        int m = m0 + ty * 4 + i;
        float k2 = g_k2[m];
        float4 outv;
        float* ov = (float*)&outv;
#pragma unroll
        for (int j = 0; j < 4; j++) {
            float cv = k2 + g_x2[n + j] - 2.0f * acc[i][j];
            ov[j] = fmaxf(cv, 0.0f);
        }
        int srow = m + (n >> 3);               // skew
        *(float4*)(g_S + (size_t)srow * I_LEN + n) = outv;
    }
}

// ---------------------------------------------------------------------------
// Kernel 3: register-systolic DTW. 32 single-warp CTAs; thread g handles
// columns [8g, 8g+8); at step s it computes row s-g. All deps are either own
// registers (prev row), shfl_up (left/diag boundary), or a cross-CTA L2 slot.
// ---------------------------------------------------------------------------
__global__ __launch_bounds__(32, 1) void dtw_systolic(float* __restrict__ out) {
    const float INF = CUDART_INF_F;
    const int w    = blockIdx.x;
    const int lane = threadIdx.x;
    const int s0   = w * 32;
    const size_t colbase = ((size_t)w * 32 + lane) * CPT;

    float Dp[CPT];
#pragma unroll
    for (int j = 0; j < CPT; j++) Dp[j] = INF;
    // bprev = D[row-1][col_left-1]; for cell (0,0) that's D[-1][-1] = 0
    float bprev = (w == 0 && lane == 0) ? 0.0f : INF;

    // 3-deep cost prefetch ring (L2-latency cover)
    float4 buf0[2], buf1[2], buf2[2];
    {
        const float* p0 = g_S + (size_t)(s0 + 0) * I_LEN + colbase;
        const float* p1 = g_S + (size_t)(s0 + 1) * I_LEN + colbase;
        const float* p2 = g_S + (size_t)(s0 + 2) * I_LEN + colbase;
        buf0[0] = *(const float4*)p0; buf0[1] = *(const float4*)(p0 + 4);
        buf1[0] = *(const float4*)p1; buf1[1] = *(const float4*)(p1 + 4);
        buf2[0] = *(const float4*)p2; buf2[1] = *(const float4*)(p2 + 4);
    }
    // boundary prefetch (lane 0 of CTAs > 0)
    unsigned long long nb = 0;
    if (lane == 0 && w > 0) nb = ld_acq(&g_bnd[w - 1][s0 - 1]);

#define STEP(T, CB)                                                            \
    {                                                                          \
        const int t = (T);                                                     \
        const int s = s0 + t;                                                  \
        float b_in = __shfl_up_sync(0xffffffffu, Dp[CPT - 1], 1);              \
        if (lane == 0) {                                                       \
            if (w == 0) b_in = INF;                                            \
            else if (t < K_LEN) {                                              \
                unsigned long long v = nb;                                     \
                while ((unsigned)v != (unsigned)s)                             \
                    v = ld_acq(&g_bnd[w - 1][s - 1]);                          \
                b_in = __uint_as_float((unsigned)(v >> 32));                   \
            } else b_in = INF;                                                 \
        }                                                                      \
        if (lane == 0 && w > 0 && t + 1 < K_LEN) nb = ld_acq(&g_bnd[w - 1][s]);\
        float c0 = CB[0].x, c1 = CB[0].y, c2 = CB[0].z, c3 = CB[0].w;          \
        float c4 = CB[1].x, c5 = CB[1].y, c6 = CB[1].z, c7 = CB[1].w;          \
        float Dn[CPT];                                                         \
        float run = fminf(b_in, fminf(bprev, Dp[0])) + c0;                     \
        Dn[0] = run;                                                           \
        run = fminf(run, fminf(Dp[0], Dp[1])) + c1; Dn[1] = run;               \
        run = fminf(run, fminf(Dp[1], Dp[2])) + c2; Dn[2] = run;               \
        run = fminf(run, fminf(Dp[2], Dp[3])) + c3; Dn[3] = run;               \
        run = fminf(run, fminf(Dp[3], Dp[4])) + c4; Dn[4] = run;               \
        run = fminf(run, fminf(Dp[4], Dp[5])) + c5; Dn[5] = run;               \
        run = fminf(run, fminf(Dp[5], Dp[6])) + c6; Dn[6] = run;               \
        run = fminf(run, fminf(Dp[6], Dp[7])) + c7; Dn[7] = run;               \
        bool valid = (t >= lane) && (t - lane < K_LEN);                        \
        _Pragma("unroll")                                                      \
        for (int j = 0; j < CPT; j++) Dp[j] = valid ? Dn[j] : INF;             \
        bprev = b_in;                                                          \
        if (lane == 31 && w < NW - 1)                                          \
            st_rel(&g_bnd[w][s],                                               \
                   ((unsigned long long)__float_as_uint(Dp[CPT - 1]) << 32)    \
                       | (unsigned)(s + 1));                                   \
        if (w == NW - 1 && lane == 31 && t == K_LEN - 1 + 31)                  \
            out[0] = Dp[CPT - 1];                                              \
        if (t + 3 < STEPS_PAD) {                                               \
            const float* p = g_S + (size_t)(s + 3) * I_LEN + colbase;          \
            CB[0] = *(const float4*)p;                                         \
            CB[1] = *(const float4*)(p + 4);                                   \
        }                                                                      \
    }

    for (int tt = 0; tt < STEPS_PAD; tt += 3) {
        STEP(tt + 0, buf0)
        STEP(tt + 1, buf1)
        STEP(tt + 2, buf2)
    }
#undef STEP
}

// ---------------------------------------------------------------------------
extern "C" void kernel_launch(void* const* d_in, const int* in_sizes, int n_in,
                              void* d_out, int out_size) {
    const float* kern = (const float*)d_in[0];
    const float* x    = (const float*)d_in[1];
    if (n_in >= 2 && in_sizes[0] == I_LEN * DIM && in_sizes[1] == K_LEN * DIM) {
        kern = (const float*)d_in[1];
        x    = (const float*)d_in[0];
    }

    int nwarp_rows = K_LEN + I_LEN;
    norms_kernel<<<(nwarp_rows + 7) / 8, 256>>>(kern, x, (float*)d_out, out_size);

    dim3 grid(I_LEN / BN, K_LEN / BM);
    cost_gemm<<<grid, 256>>>(kern, x);

    dtw_systolic<<<NW, 32>>>((float*)d_out);
}

// round 4
// speedup vs baseline: 1.7216x; 1.7216x over previous
#include <cuda_runtime.h>
#include <math_constants.h>

#define K_LEN 1024
#define I_LEN 8192
#define DIM   128

#define TPB   256               // DP threads (one CTA)
#define CPT   32                // columns per thread; 256*32 = 8192
#define NWRP  8                 // warps in the DP CTA
#define STEPS 1286              // K_LEN - 1 + p_max(262) + 1
#define SROWS 1288
#define CANARY 0x7FC00001u      // NaN payload; real D values are never NaN

// Scratch (alloc-free rule: __device__ globals)
// Skewed cost: S[m + p(n)][n] = C[m][n], p(n) = n/32 + n/1024 (per-warp +1 skew)
__device__ float g_S[SROWS * I_LEN];   // 42 MB
__device__ float g_k2[K_LEN];
__device__ float g_x2[I_LEN];

// ---------------------------------------------------------------------------
// Kernel 1: row norms + INF top-triangle of skewed matrix + zero extra outs.
// ---------------------------------------------------------------------------
__global__ void norms_kernel(const float* __restrict__ kern,
                             const float* __restrict__ x,
                             float* __restrict__ out, int out_size) {
    int gtid = blockIdx.x * blockDim.x + threadIdx.x;
    if (gtid < out_size) out[gtid] = 0.0f;    // out[0] overwritten by DP

    // INF triangle: for column-group g (thread id in DP), rows s < p(g) are
    // invalid (r = s - p < 0) and must read +INF so the DP needs no masking.
    if (gtid < 256 * 264) {
        int g    = gtid / 264;
        int srow = gtid % 264;
        int p    = g + (g >> 5);
        if (srow < p) {
            float4 inf4 = make_float4(CUDART_INF_F, CUDART_INF_F,
                                      CUDART_INF_F, CUDART_INF_F);
            float4* dst = (float4*)(g_S + (size_t)srow * I_LEN + g * CPT);
#pragma unroll
            for (int i = 0; i < 8; i++) dst[i] = inf4;
        }
    }

    int warp = gtid >> 5;
    int lane = threadIdx.x & 31;
    if (warp >= K_LEN + I_LEN) return;
    const float* row = (warp < K_LEN) ? (kern + warp * DIM)
                                      : (x + (warp - K_LEN) * DIM);
    float4 v = ((const float4*)row)[lane];
    float s = v.x * v.x + v.y * v.y + v.z * v.z + v.w * v.w;
#pragma unroll
    for (int off = 16; off; off >>= 1) s += __shfl_xor_sync(0xffffffffu, s, off);
    if (lane == 0) {
        if (warp < K_LEN) g_k2[warp] = s;
        else              g_x2[warp - K_LEN] = s;
    }
}

// ---------------------------------------------------------------------------
// Kernel 2: skewed cost S[m + p(n)][n] = max(k2[m]+x2[n]-2<a_m,b_n>, 0)
// Plain scalar-FFMA tiled SGEMM (R1 version); only the epilogue is skewed.
// ---------------------------------------------------------------------------
#define BM 64
#define BN 64
#define BK 64

__global__ __launch_bounds__(256) void cost_gemm(const float* __restrict__ A,
                                                 const float* __restrict__ B) {
    __shared__ float As[BK][BM + 4];
    __shared__ float Bs[BK][BN + 4];
    const int tx = threadIdx.x & 15;
    const int ty = threadIdx.x >> 4;
    const int m0 = blockIdx.y * BM;
    const int n0 = blockIdx.x * BN;
    const int t  = threadIdx.x;

    float acc[4][4] = {};

    for (int k0 = 0; k0 < DIM; k0 += BK) {
#pragma unroll
        for (int i = 0; i < 4; i++) {
            int idx = t + i * 256;
            int row = idx >> 4;
            int c4  = idx & 15;
            float4 va = *(const float4*)(A + (size_t)(m0 + row) * DIM + k0 + c4 * 4);
            As[c4 * 4 + 0][row] = va.x;
            As[c4 * 4 + 1][row] = va.y;
            As[c4 * 4 + 2][row] = va.z;
            As[c4 * 4 + 3][row] = va.w;
            float4 vb = *(const float4*)(B + (size_t)(n0 + row) * DIM + k0 + c4 * 4);
            Bs[c4 * 4 + 0][row] = vb.x;
            Bs[c4 * 4 + 1][row] = vb.y;
            Bs[c4 * 4 + 2][row] = vb.z;
            Bs[c4 * 4 + 3][row] = vb.w;
        }
        __syncthreads();
#pragma unroll 16
        for (int kk = 0; kk < BK; kk++) {
            float a[4], b[4];
            *(float4*)a = *(const float4*)&As[kk][ty * 4];
            *(float4*)b = *(const float4*)&Bs[kk][tx * 4];
#pragma unroll
            for (int i = 0; i < 4; i++)
#pragma unroll
                for (int j = 0; j < 4; j++)
                    acc[i][j] += a[i] * b[j];
        }
        __syncthreads();
    }

    const int n = n0 + tx * 4;       // 4 cols never cross a 32-col group
    const int pskew = (n >> 5) + (n >> 10);
#pragma unroll
    for (int i = 0; i < 4; i++) {
        int m = m0 + ty * 4 + i;
        float k2 = g_k2[m];
        float4 outv;
        float* ov = (float*)&outv;
#pragma unroll
        for (int j = 0; j < 4; j++) {
            float cv = k2 + g_x2[n + j] - 2.0f * acc[i][j];
            ov[j] = fmaxf(cv, 0.0f);
        }
        *(float4*)(g_S + (size_t)(m + pskew) * I_LEN + n) = outv;
    }
}

// ---------------------------------------------------------------------------
// Kernel 3: register-systolic DTW, ONE CTA of 256 threads, 32 cols/thread.
// Thread tid sits at position p = tid + warp; at step s it computes row
// r = s - p of its 32 columns. Deps: own regs (up), running chain (left),
// shfl_up of prev step (intra-warp boundary), write-once volatile smem slot
// from producer step s-2 (cross-warp boundary, canary-tagged). No barriers.
// Invalid top cells read +INF costs (pre-filled) -> no masking needed.
// ---------------------------------------------------------------------------
__global__ __launch_bounds__(TPB, 1) void dtw_systolic(float* __restrict__ out) {
    __shared__ volatile unsigned int slots[NWRP - 1][STEPS];   // 36 KB
    const float INF = CUDART_INF_F;
    const int tid  = threadIdx.x;
    const int lane = tid & 31;
    const int w    = tid >> 5;
    const int p    = tid + w;
    const size_t colbase = (size_t)tid * CPT;

    for (int i = tid; i < (NWRP - 1) * STEPS; i += TPB)
        ((volatile unsigned int*)slots)[i] = CANARY;
    __syncthreads();

    float Dp[CPT];
#pragma unroll
    for (int j = 0; j < CPT; j++) Dp[j] = INF;
    float bprev = (tid == 0) ? 0.0f : INF;   // diag D[r-1][col0-1]; (0,0) -> 0
    float lastD = INF;                       // own Dp[31] of previous step

    float4 cu[8], nx[8];
    {
        const float4* p0 = (const float4*)(g_S + colbase);
        const float4* p1 = (const float4*)(g_S + (size_t)I_LEN + colbase);
#pragma unroll
        for (int i = 0; i < 8; i++) cu[i] = p0[i];
#pragma unroll
        for (int i = 0; i < 8; i++) nx[i] = p1[i];
    }

#define STEP(S_, CB, NB)                                                       \
    {                                                                          \
        const int s = (S_);                                                    \
        float shf = __shfl_up_sync(0xffffffffu, lastD, 1);                     \
        float b_in;                                                            \
        if (lane == 0) {                                                       \
            int r = s - p;                                                     \
            if (w > 0 && r >= 0 && r < K_LEN) {                                \
                unsigned v = slots[w - 1][s - 2];                              \
                while (v == CANARY) v = slots[w - 1][s - 2];                   \
                b_in = __uint_as_float(v);                                     \
            } else b_in = INF;                                                 \
        } else b_in = shf;                                                     \
        const float* cc = (const float*)CB;                                    \
        float run = fminf(fminf(b_in, bprev), Dp[0]) + cc[0];                  \
        float prevOld = Dp[0];                                                 \
        Dp[0] = run;                                                           \
        _Pragma("unroll")                                                      \
        for (int j = 1; j < CPT; j++) {                                        \
            float t = fminf(prevOld, Dp[j]);                                   \
            prevOld = Dp[j];                                                   \
            run = fminf(run, t) + cc[j];                                       \
            Dp[j] = run;                                                       \
        }                                                                      \
        bprev = b_in;                                                          \
        lastD = run;                                                           \
        if (lane == 31 && w < NWRP - 1)                                        \
            slots[w][s] = __float_as_uint(run);                                \
        if (s + 2 < STEPS) {                                                   \
            const float4* np = (const float4*)(g_S + (size_t)(s + 2) * I_LEN   \
                                               + colbase);                     \
            _Pragma("unroll")                                                  \
            for (int i = 0; i < 8; i++) NB[i] = np[i];                         \
        }                                                                      \
        if (tid == TPB - 1 && s == STEPS - 1) out[0] = run;                    \
    }

    for (int ss = 0; ss < STEPS; ss += 2) {
        STEP(ss + 0, cu, cu)
        STEP(ss + 1, nx, nx)
    }
#undef STEP
}

// ---------------------------------------------------------------------------
extern "C" void kernel_launch(void* const* d_in, const int* in_sizes, int n_in,
                              void* d_out, int out_size) {
    const float* kern = (const float*)d_in[0];
    const float* x    = (const float*)d_in[1];
    if (n_in >= 2 && in_sizes[0] == I_LEN * DIM && in_sizes[1] == K_LEN * DIM) {
        kern = (const float*)d_in[1];
        x    = (const float*)d_in[0];
    }

    int nwarp_rows = K_LEN + I_LEN;
    norms_kernel<<<(nwarp_rows + 7) / 8, 256>>>(kern, x, (float*)d_out, out_size);

    dim3 grid(I_LEN / BN, K_LEN / BM);
    cost_gemm<<<grid, 256>>>(kern, x);

    dtw_systolic<<<1, TPB>>>((float*)d_out);
}

// round 5
// speedup vs baseline: 1.7251x; 1.0021x over previous
#include <cuda_runtime.h>
#include <math_constants.h>

#define K_LEN 1024
#define I_LEN 8192
#define DIM   128

#define TPB   256               // DP threads (one CTA)
#define CPT   32                // columns per thread; 256*32 = 8192
#define NWRP  8                 // warps in the DP CTA
// position of thread t: p = t + 2*warp(t); max p = 255 + 14 = 269
#define PMAX  269
#define STEPS 1293              // PMAX + K_LEN; divisible by 3
#define SROWS 1296              // prefetch reads up to row STEPS+1 = 1294
#define CANARY 0x7FC00001u      // NaN payload; real D values are never NaN

// Scratch (alloc-free rule: __device__ globals)
// Skewed cost: S[m + p(n)][n] = C[m][n], p(n) = n/32 + 2*(n/1024)
__device__ float g_S[SROWS * I_LEN];   // 42.5 MB
__device__ float g_k2[K_LEN];
__device__ float g_x2[I_LEN];

// ---------------------------------------------------------------------------
// Kernel 1: row norms + INF top-triangle of skewed matrix + zero extra outs.
// ---------------------------------------------------------------------------
__global__ void norms_kernel(const float* __restrict__ kern,
                             const float* __restrict__ x,
                             float* __restrict__ out, int out_size) {
    int gtid = blockIdx.x * blockDim.x + threadIdx.x;
    if (gtid < out_size) out[gtid] = 0.0f;    // out[0] overwritten by DP

    // INF triangle: for column-group g, rows srow < p(g) are invalid
    // (r = srow - p < 0) and must read +INF so the DP needs no masking.
    if (gtid < 256 * 272) {
        int g    = gtid / 272;
        int srow = gtid % 272;
        int p    = g + 2 * (g >> 5);
        if (srow < p) {
            float4 inf4 = make_float4(CUDART_INF_F, CUDART_INF_F,
                                      CUDART_INF_F, CUDART_INF_F);
            float4* dst = (float4*)(g_S + (size_t)srow * I_LEN + g * CPT);
#pragma unroll
            for (int i = 0; i < 8; i++) dst[i] = inf4;
        }
    }

    int warp = gtid >> 5;
    int lane = threadIdx.x & 31;
    if (warp >= K_LEN + I_LEN) return;
    const float* row = (warp < K_LEN) ? (kern + warp * DIM)
                                      : (x + (warp - K_LEN) * DIM);
    float4 v = ((const float4*)row)[lane];
    float s = v.x * v.x + v.y * v.y + v.z * v.z + v.w * v.w;
#pragma unroll
    for (int off = 16; off; off >>= 1) s += __shfl_xor_sync(0xffffffffu, s, off);
    if (lane == 0) {
        if (warp < K_LEN) g_k2[warp] = s;
        else              g_x2[warp - K_LEN] = s;
    }
}

// ---------------------------------------------------------------------------
// Kernel 2: skewed cost S[m + p(n)][n] = max(k2[m]+x2[n]-2<a_m,b_n>, 0)
// Plain scalar-FFMA tiled SGEMM; only the epilogue is skewed.
// ---------------------------------------------------------------------------
#define BM 64
#define BN 64
#define BK 64

__global__ __launch_bounds__(256) void cost_gemm(const float* __restrict__ A,
                                                 const float* __restrict__ B) {
    __shared__ float As[BK][BM + 4];
    __shared__ float Bs[BK][BN + 4];
    const int tx = threadIdx.x & 15;
    const int ty = threadIdx.x >> 4;
    const int m0 = blockIdx.y * BM;
    const int n0 = blockIdx.x * BN;
    const int t  = threadIdx.x;

    float acc[4][4] = {};

    for (int k0 = 0; k0 < DIM; k0 += BK) {
#pragma unroll
        for (int i = 0; i < 4; i++) {
            int idx = t + i * 256;
            int row = idx >> 4;
            int c4  = idx & 15;
            float4 va = *(const float4*)(A + (size_t)(m0 + row) * DIM + k0 + c4 * 4);
            As[c4 * 4 + 0][row] = va.x;
            As[c4 * 4 + 1][row] = va.y;
            As[c4 * 4 + 2][row] = va.z;
            As[c4 * 4 + 3][row] = va.w;
            float4 vb = *(const float4*)(B + (size_t)(n0 + row) * DIM + k0 + c4 * 4);
            Bs[c4 * 4 + 0][row] = vb.x;
            Bs[c4 * 4 + 1][row] = vb.y;
            Bs[c4 * 4 + 2][row] = vb.z;
            Bs[c4 * 4 + 3][row] = vb.w;
        }
        __syncthreads();
#pragma unroll 16
        for (int kk = 0; kk < BK; kk++) {
            float a[4], b[4];
            *(float4*)a = *(const float4*)&As[kk][ty * 4];
            *(float4*)b = *(const float4*)&Bs[kk][tx * 4];
#pragma unroll
            for (int i = 0; i < 4; i++)
#pragma unroll
                for (int j = 0; j < 4; j++)
                    acc[i][j] += a[i] * b[j];
        }
        __syncthreads();
    }

    const int n = n0 + tx * 4;       // 4 cols never cross a 32-col group
    const int pskew = (n >> 5) + 2 * (n >> 10);
#pragma unroll
    for (int i = 0; i < 4; i++) {
        int m = m0 + ty * 4 + i;
        float k2 = g_k2[m];
        float4 outv;
        float* ov = (float*)&outv;
#pragma unroll
        for (int j = 0; j < 4; j++) {
            float cv = k2 + g_x2[n + j] - 2.0f * acc[i][j];
            ov[j] = fmaxf(cv, 0.0f);
        }
        *(float4*)(g_S + (size_t)(m + pskew) * I_LEN + n) = outv;
    }
}

// ---------------------------------------------------------------------------
// Kernel 3: register-systolic DTW, ONE CTA of 256 threads, 32 cols/thread.
// Thread tid at position p = tid + 2*warp; at step s it computes row r = s-p
// of its 32 columns. Deps: own regs (up/diag), running chain (left), shfl_up
// of prev step (intra-warp boundary), write-once volatile smem slot from
// producer step s-3 (cross-warp, canary-tagged, 2 intervals of slack).
// Cost prefetch: loads for row s+2 issue at the TOP of step s into the buffer
// consumed at step s-1 (disjoint registers; ~2 intervals of slack).
// Invalid top cells read +INF costs (pre-filled) -> no masking needed.
// ---------------------------------------------------------------------------
__global__ __launch_bounds__(TPB, 1) void dtw_systolic(float* __restrict__ out) {
    __shared__ volatile unsigned int slots[NWRP - 1][STEPS];   // ~36 KB
    const float INF = CUDART_INF_F;
    const int tid  = threadIdx.x;
    const int lane = tid & 31;
    const int w    = tid >> 5;
    const int p    = tid + 2 * w;
    const size_t colbase = (size_t)tid * CPT;

    for (int i = tid; i < (NWRP - 1) * STEPS; i += TPB)
        ((volatile unsigned int*)slots)[i] = CANARY;
    __syncthreads();

    float Dp[CPT];
#pragma unroll
    for (int j = 0; j < CPT; j++) Dp[j] = INF;
    float bprev = (tid == 0) ? 0.0f : INF;   // diag D[r-1][col0-1]; (0,0) -> 0
    float lastD = INF;                       // own Dp[31] of previous step

    float4 B0[8], B1[8], B2[8];
    {
        const float4* p0 = (const float4*)(g_S + colbase);
        const float4* p1 = (const float4*)(g_S + (size_t)I_LEN + colbase);
#pragma unroll
        for (int i = 0; i < 8; i++) B0[i] = p0[i];
#pragma unroll
        for (int i = 0; i < 8; i++) B1[i] = p1[i];
    }

#define STEP(S_, CUR, PF)                                                      \
    {                                                                          \
        const int s = (S_);                                                    \
        /* prefetch row s+2 first: disjoint regs, max slack */                 \
        {                                                                      \
            const float4* np =                                                 \
                (const float4*)(g_S + (size_t)(s + 2) * I_LEN + colbase);      \
            _Pragma("unroll")                                                  \
            for (int i = 0; i < 8; i++) PF[i] = np[i];                         \
        }                                                                      \
        float shf = __shfl_up_sync(0xffffffffu, lastD, 1);                     \
        float b_in;                                                            \
        if (lane == 0) {                                                       \
            int r = s - p;                                                     \
            if (w > 0 && r >= 0 && r < K_LEN) {                                \
                unsigned v = slots[w - 1][s - 3];                              \
                while (v == CANARY) v = slots[w - 1][s - 3];                   \
                b_in = __uint_as_float(v);                                     \
            } else b_in = INF;                                                 \
        } else b_in = shf;                                                     \
        const float* cc = (const float*)CUR;                                   \
        float run = fminf(fminf(b_in, bprev), Dp[0]) + cc[0];                  \
        float prevOld = Dp[0];                                                 \
        Dp[0] = run;                                                           \
        _Pragma("unroll")                                                      \
        for (int j = 1; j < CPT; j++) {                                        \
            float t = fminf(prevOld, Dp[j]);                                   \
            prevOld = Dp[j];                                                   \
            run = fminf(run, t) + cc[j];                                       \
            Dp[j] = run;                                                       \
        }                                                                      \
        bprev = b_in;                                                          \
        lastD = run;                                                           \
        if (lane == 31 && w < NWRP - 1)                                        \
            slots[w][s] = __float_as_uint(run);                                \
        if (tid == TPB - 1 && s == STEPS - 1) out[0] = run;                    \
    }

    for (int ss = 0; ss < STEPS; ss += 3) {
        STEP(ss + 0, B0, B2)
        STEP(ss + 1, B1, B0)
        STEP(ss + 2, B2, B1)
    }
#undef STEP
}

// ---------------------------------------------------------------------------
extern "C" void kernel_launch(void* const* d_in, const int* in_sizes, int n_in,
                              void* d_out, int out_size) {
    const float* kern = (const float*)d_in[0];
    const float* x    = (const float*)d_in[1];
    if (n_in >= 2 && in_sizes[0] == I_LEN * DIM && in_sizes[1] == K_LEN * DIM) {
        kern = (const float*)d_in[1];
        x    = (const float*)d_in[0];
    }

    int nwarp_rows = K_LEN + I_LEN;
    norms_kernel<<<(nwarp_rows + 7) / 8, 256>>>(kern, x, (float*)d_out, out_size);

    dim3 grid(I_LEN / BN, K_LEN / BM);
    cost_gemm<<<grid, 256>>>(kern, x);

    dtw_systolic<<<1, TPB>>>((float*)d_out);
}